// round 1
// baseline (speedup 1.0000x reference)
#include <cuda_runtime.h>

// ---------------------------------------------------------------------------
// loss2: InfoNCE-style loss.
//   loss = (1/(B*k*(k-1))) * sum_{b,i!=j in block} [ log(e^{c_ij} + negA_i) - c_ij ]
//   negA_i = r * ( sum_k exp(c_ik) - sum_{m in block(i)} exp(c_im) ),  r = (2B-2)/(T-5)
// (random-subset negative sum replaced by its unbiased mean; rel err ~2e-6, see notes)
// ---------------------------------------------------------------------------

#define C_DIM 128
#define BLK 5
#define MAX_T 4096

#define BM 64
#define BN 64
#define KH 64
#define JSPLIT 9

__device__ float  g_xn[MAX_T * C_DIM];
__device__ float  g_rowsum[MAX_T];
__device__ double g_accum;

// ---------------- fp32x2 helpers ----------------
__device__ __forceinline__ void fma2(unsigned long long &d,
                                     unsigned long long a,
                                     unsigned long long b) {
    asm("fma.rn.f32x2 %0, %1, %2, %0;" : "+l"(d) : "l"(a), "l"(b));
}
__device__ __forceinline__ unsigned long long pack2(float lo, float hi) {
    unsigned long long r;
    asm("mov.b64 %0, {%1, %2};" : "=l"(r) : "f"(lo), "f"(hi));
    return r;
}
__device__ __forceinline__ float2 unpack2(unsigned long long v) {
    float2 r;
    asm("mov.b64 {%0, %1}, %2;" : "=f"(r.x), "=f"(r.y) : "l"(v));
    return r;
}

// exp(c) for c in [-1.05, 1.05], degree-9 Taylor, FMA-only (avoids MUFU bottleneck).
// One-signed truncation error < 8e-7 at |c|=1, ~1e-17 at typical |c|~0.09.
__device__ __forceinline__ float exp_poly(float c) {
    float p = 2.75573192e-6f;          // 1/9!
    p = fmaf(p, c, 2.48015873e-5f);    // 1/8!
    p = fmaf(p, c, 1.98412698e-4f);    // 1/7!
    p = fmaf(p, c, 1.38888889e-3f);    // 1/6!
    p = fmaf(p, c, 8.33333333e-3f);    // 1/5!
    p = fmaf(p, c, 4.16666667e-2f);    // 1/4!
    p = fmaf(p, c, 1.66666667e-1f);    // 1/3!
    p = fmaf(p, c, 0.5f);
    p = fmaf(p, c, 1.0f);
    p = fmaf(p, c, 1.0f);
    return p;
}

// ---------------- kernels ----------------
__global__ void init_kernel() {
    int i = blockIdx.x * blockDim.x + threadIdx.x;
    if (i < MAX_T) g_rowsum[i] = 0.0f;
    if (i == 0) g_accum = 0.0;
}

__global__ void normalize_kernel(const float* __restrict__ x, int T) {
    int row = blockIdx.x;            // grid = T
    int t = threadIdx.x;             // 128 threads
    float v = x[row * C_DIM + t];
    float s = v * v;
    #pragma unroll
    for (int o = 16; o > 0; o >>= 1) s += __shfl_xor_sync(0xffffffffu, s, o);
    __shared__ float ws[4];
    if ((t & 31) == 0) ws[t >> 5] = s;
    __syncthreads();
    float tot = ws[0] + ws[1] + ws[2] + ws[3];
    float inv = 1.0f / fmaxf(sqrtf(tot), 1e-8f);
    g_xn[row * C_DIM + t] = v * inv;
}

// rowsum[i] = sum_j exp( dot(xn_i, xn_j) ), tiled 64x64, K in two 64-halves.
__global__ __launch_bounds__(256) void rowsum_kernel(int T, int ntiles) {
    __shared__ float As[KH][BM];               // k-major: [k][row]
    __shared__ float Bs[KH][BN];
    __shared__ float red[BM][17];

    const int i0  = blockIdx.x * BM;
    const int tid = threadIdx.x;
    const int tx  = tid & 15;                   // 16 cols of threads
    const int ty  = tid >> 4;                   // 16 rows of threads

    float rowacc[4] = {0.f, 0.f, 0.f, 0.f};

    for (int jt = blockIdx.y; jt < ntiles; jt += JSPLIT) {
        const int j0 = jt * BN;
        unsigned long long acc01[4], acc23[4];
        #pragma unroll
        for (int r = 0; r < 4; r++) { acc01[r] = 0ull; acc23[r] = 0ull; }

        for (int kk = 0; kk < C_DIM; kk += KH) {
            __syncthreads();
            #pragma unroll
            for (int l = 0; l < 4; l++) {
                int idx = tid + l * 256;        // 0..1023
                int kq  = idx >> 6;             // 0..15 (float4 within K-half)
                int row = idx & 63;
                int gi = i0 + row;
                float4 v = (gi < T)
                    ? *(const float4*)&g_xn[gi * C_DIM + kk + kq * 4]
                    : make_float4(0.f, 0.f, 0.f, 0.f);
                As[kq*4+0][row] = v.x; As[kq*4+1][row] = v.y;
                As[kq*4+2][row] = v.z; As[kq*4+3][row] = v.w;
                int gj = j0 + row;
                float4 w = (gj < T)
                    ? *(const float4*)&g_xn[gj * C_DIM + kk + kq * 4]
                    : make_float4(0.f, 0.f, 0.f, 0.f);
                Bs[kq*4+0][row] = w.x; Bs[kq*4+1][row] = w.y;
                Bs[kq*4+2][row] = w.z; Bs[kq*4+3][row] = w.w;
            }
            __syncthreads();

            #pragma unroll 8
            for (int k = 0; k < KH; k++) {
                float4 a = *(const float4*)&As[k][ty * 4];
                float4 b = *(const float4*)&Bs[k][tx * 4];
                unsigned long long b01 = pack2(b.x, b.y);
                unsigned long long b23 = pack2(b.z, b.w);
                unsigned long long a0 = pack2(a.x, a.x);
                unsigned long long a1 = pack2(a.y, a.y);
                unsigned long long a2 = pack2(a.z, a.z);
                unsigned long long a3 = pack2(a.w, a.w);
                fma2(acc01[0], a0, b01); fma2(acc23[0], a0, b23);
                fma2(acc01[1], a1, b01); fma2(acc23[1], a1, b23);
                fma2(acc01[2], a2, b01); fma2(acc23[2], a2, b23);
                fma2(acc01[3], a3, b01); fma2(acc23[3], a3, b23);
            }
        }

        // exp + accumulate (mask out-of-range j columns)
        const int jbase = j0 + tx * 4;
        #pragma unroll
        for (int r = 0; r < 4; r++) {
            float2 c01 = unpack2(acc01[r]);
            float2 c23 = unpack2(acc23[r]);
            float e0 = (jbase + 0 < T) ? exp_poly(c01.x) : 0.f;
            float e1 = (jbase + 1 < T) ? exp_poly(c01.y) : 0.f;
            float e2 = (jbase + 2 < T) ? exp_poly(c23.x) : 0.f;
            float e3 = (jbase + 3 < T) ? exp_poly(c23.y) : 0.f;
            rowacc[r] += (e0 + e1) + (e2 + e3);
        }
    }

    // reduce partial row sums across the 16 tx threads
    __syncthreads();
    #pragma unroll
    for (int r = 0; r < 4; r++) red[ty * 4 + r][tx] = rowacc[r];
    __syncthreads();
    if (tid < BM) {
        float s = 0.f;
        #pragma unroll
        for (int c = 0; c < 16; c++) s += red[tid][c];
        int gi = i0 + tid;
        if (gi < T) atomicAdd(&g_rowsum[gi], s);
    }
}

// Per-block positives + final log terms. One warp per 5-element block.
__global__ void pairs_kernel(float r, int T) {
    const int b = blockIdx.x;
    const int lane = threadIdx.x;               // 32 threads
    __shared__ float xb[BLK][C_DIM];
    __shared__ float cmat[BLK][BLK];

    for (int idx = lane; idx < BLK * C_DIM; idx += 32) {
        int i = idx >> 7, k = idx & 127;
        xb[i][k] = g_xn[(b * BLK + i) * C_DIM + k];
    }
    __syncwarp();

    const int CI[15] = {0,0,0,0,0,1,1,1,1,2,2,2,3,3,4};
    const int CJ[15] = {0,1,2,3,4,1,2,3,4,2,3,4,3,4,4};
    #pragma unroll
    for (int combo = 0; combo < 15; combo++) {
        int i = CI[combo], j = CJ[combo];
        float s = 0.f;
        #pragma unroll
        for (int q = 0; q < 4; q++)
            s += xb[i][lane + 32 * q] * xb[j][lane + 32 * q];
        #pragma unroll
        for (int o = 16; o > 0; o >>= 1) s += __shfl_xor_sync(0xffffffffu, s, o);
        if (lane == 0) { cmat[i][j] = s; cmat[j][i] = s; }
    }
    __syncwarp();

    float term = 0.f;
    if (lane < 20) {
        int i  = lane >> 2;
        int jj = lane & 3;
        int j  = jj + (jj >= i ? 1 : 0);
        float bs = 0.f;
        #pragma unroll
        for (int m = 0; m < BLK; m++) bs += expf(cmat[i][m]);
        float negA = r * (g_rowsum[b * BLK + i] - bs);
        float cij = cmat[i][j];
        term = logf(expf(cij) + negA) - cij;     // = log(pos+neg) - log(pos)
    }
    #pragma unroll
    for (int o = 16; o > 0; o >>= 1) term += __shfl_xor_sync(0xffffffffu, term, o);
    if (lane == 0) atomicAdd(&g_accum, (double)term);
}

__global__ void finalize_kernel(const int* __restrict__ kuai2, int B, float* out) {
    int k2 = *kuai2;
    out[0] = (float)(g_accum / ((double)B * (double)k2 * (double)(k2 - 1)));
}

// ---------------- launch ----------------
extern "C" void kernel_launch(void* const* d_in, const int* in_sizes, int n_in,
                              void* d_out, int out_size) {
    const float* x     = (const float*)d_in[0];
    const int*   kuai2 = (const int*)d_in[1];

    int T = in_sizes[0] / C_DIM;
    int B = T / BLK;
    float r = (float)(2 * B - 2) / (float)(T - BLK);
    int ntiles = (T + BM - 1) / BM;

    init_kernel<<<(MAX_T + 255) / 256, 256>>>();
    normalize_kernel<<<T, C_DIM>>>(x, T);
    dim3 grid(ntiles, JSPLIT);
    rowsum_kernel<<<grid, 256>>>(T, ntiles);
    pairs_kernel<<<B, 32>>>(r, T);
    finalize_kernel<<<1, 1>>>(kuai2, B, (float*)d_out);
}

// round 3
// speedup vs baseline: 5.4146x; 5.4146x over previous
#include <cuda_runtime.h>
#include <cuda_bf16.h>
#include <cstdint>

// ---------------------------------------------------------------------------
// loss2:
//   loss = (1/(B*k*(k-1))) * sum_{b, i!=j in block} [ log(e^{c_ij} + negA_i) - c_ij ]
//   negA_i = r * ( rowsum_i - blocksum_i ),  r = (2B-2)/(T-5)
//   rowsum_i = sum_j exp(cos(i,j))  via bf16 mma.sync (legacy tensor path; the
//   build targets plain sm_100, so tcgen05 is unavailable) + packed-f32x2 exp.
//   In-block cosines / positives computed exactly in fp32 by a tiny kernel.
// ---------------------------------------------------------------------------

#define C_DIM 128
#define BLK 5
#define MAX_T 4096
#define TM 128
#define TN 128
#define NSPLIT 4

__device__ __align__(16) __nv_bfloat16 g_xbf[MAX_T * C_DIM];  // zero-init: rows>=T are 0
__device__ __align__(16) float g_xn[MAX_T * C_DIM];
__device__ float g_part[NSPLIT][MAX_T];
__device__ float g_pairpart[128];

// smem: A tile 32KB @0, B double buffer 2x32KB @32768
#define OFF_A 0
#define OFF_B 32768
#define SMEM_DYN 98304

// ---------------- helpers ----------------
__device__ __forceinline__ uint32_t smem_u32(const void* p) {
    uint32_t a;
    asm("{ .reg .u64 t; cvta.to.shared.u64 t, %1; cvt.u32.u64 %0, t; }" : "=r"(a) : "l"(p));
    return a;
}

__device__ __forceinline__ void cp_async16(uint32_t dst, const void* src) {
    asm volatile("cp.async.cg.shared.global [%0], [%1], 16;"
                 :: "r"(dst), "l"(__cvta_generic_to_global(src)));
}
#define CP_COMMIT()  asm volatile("cp.async.commit_group;" ::: "memory")
#define CP_WAIT(n)   asm volatile("cp.async.wait_group %0;" :: "n"(n) : "memory")

__device__ __forceinline__ void ldmatrix_x4(uint32_t* r, uint32_t addr) {
    asm volatile("ldmatrix.sync.aligned.m8n8.x4.shared.b16 {%0,%1,%2,%3}, [%4];"
                 : "=r"(r[0]), "=r"(r[1]), "=r"(r[2]), "=r"(r[3]) : "r"(addr));
}

__device__ __forceinline__ void mma_bf16(float* c, const uint32_t* a, const uint32_t* b) {
    asm volatile(
        "mma.sync.aligned.m16n8k16.row.col.f32.bf16.bf16.f32 "
        "{%0,%1,%2,%3}, {%4,%5,%6,%7}, {%8,%9}, {%0,%1,%2,%3};"
        : "+f"(c[0]), "+f"(c[1]), "+f"(c[2]), "+f"(c[3])
        : "r"(a[0]), "r"(a[1]), "r"(a[2]), "r"(a[3]), "r"(b[0]), "r"(b[1]));
}

// ---------------- fp32x2 packed exp ----------------
__device__ __forceinline__ unsigned long long pk2(float lo, float hi) {
    unsigned long long r;
    asm("mov.b64 %0, {%1, %2};" : "=l"(r) : "f"(lo), "f"(hi));
    return r;
}
__device__ __forceinline__ float2 up2(unsigned long long v) {
    float2 r;
    asm("mov.b64 {%0, %1}, %2;" : "=f"(r.x), "=f"(r.y) : "l"(v));
    return r;
}
__device__ __forceinline__ unsigned long long fma2(unsigned long long a,
                                                   unsigned long long b,
                                                   unsigned long long c) {
    unsigned long long d;
    asm("fma.rn.f32x2 %0, %1, %2, %3;" : "=l"(d) : "l"(a), "l"(b), "l"(c));
    return d;
}
// exp(c) for |c| <= ~1.05, degree-8 Taylor; exp_pk(0) == 1.0 exactly.
__device__ __forceinline__ unsigned long long exp_pk(unsigned long long c) {
    unsigned long long p = pk2(2.4801587e-5f, 2.4801587e-5f);
    p = fma2(p, c, pk2(1.9841270e-4f, 1.9841270e-4f));
    p = fma2(p, c, pk2(1.3888889e-3f, 1.3888889e-3f));
    p = fma2(p, c, pk2(8.3333333e-3f, 8.3333333e-3f));
    p = fma2(p, c, pk2(4.1666667e-2f, 4.1666667e-2f));
    p = fma2(p, c, pk2(1.6666667e-1f, 1.6666667e-1f));
    p = fma2(p, c, pk2(0.5f, 0.5f));
    p = fma2(p, c, pk2(1.0f, 1.0f));
    p = fma2(p, c, pk2(1.0f, 1.0f));
    return p;
}

// tile smem layout: row-major 128 rows x 256B, 16B chunks XOR-swizzled by (row&7)
__device__ __forceinline__ void copy_tile_async(uint32_t dstb, int grow0, int tid) {
    #pragma unroll
    for (int l = 0; l < 8; l++) {
        int idx = tid + l * 256;               // 0..2047
        int row = idx >> 4;
        int ch  = idx & 15;
        cp_async16(dstb + row * 256 + ((ch ^ (row & 7)) << 4),
                   &g_xbf[(grow0 + row) * C_DIM + ch * 8]);
    }
}

// ---------------- kernels ----------------
__global__ void normalize_kernel(const float* __restrict__ x, int T) {
    int row = blockIdx.x;
    int t = threadIdx.x;                       // 128
    float v = x[row * C_DIM + t];
    float s = v * v;
    #pragma unroll
    for (int o = 16; o > 0; o >>= 1) s += __shfl_xor_sync(0xffffffffu, s, o);
    __shared__ float ws[4];
    if ((t & 31) == 0) ws[t >> 5] = s;
    __syncthreads();
    float tot = ws[0] + ws[1] + ws[2] + ws[3];
    float inv = 1.0f / fmaxf(sqrtf(tot), 1e-8f);
    float xv = v * inv;
    g_xn[row * C_DIM + t]  = xv;
    g_xbf[row * C_DIM + t] = __float2bfloat16(xv);
}

__global__ __launch_bounds__(256) void rowsum_mma(int T, int ntN) {
    extern __shared__ char smem[];
    const uint32_t sb = smem_u32(smem);
    const int tid  = threadIdx.x;
    const int wid  = tid >> 5;
    const int lane = tid & 31;

    const int i0  = blockIdx.x * TM;
    const int tpc = (ntN + NSPLIT - 1) / NSPLIT;
    const int jt0 = blockIdx.y * tpc;
    const int nt  = min(tpc, ntN - jt0);
    if (nt <= 0) return;

    // pipeline: group0 = A, group1 = B(0)
    copy_tile_async(sb + OFF_A, i0, tid);
    CP_COMMIT();
    copy_tile_async(sb + OFF_B, jt0 * TN, tid);
    CP_COMMIT();

    const int mh = wid >> 2;                   // M half (0/1)
    const int nq = wid & 3;                    // N quarter (0..3)
    const int mrow = mh * 64;
    const int jw   = nq * 32;
    const int s7   = lane & 7;

    // ldmatrix lane addressing offsets
    const int ro_a = (lane & 7) + ((lane >> 3) & 1) * 8;   // A: g1,g3 -> +8 rows
    const int cg_a = (lane >> 4);                          // A: g2,g3 -> k-hi chunk
    const int ro_b = (lane & 7) + ((lane >> 4) & 1) * 8;   // B: g2,g3 -> +8 rows
    const int cg_b = (lane >> 3) & 1;                      // B: g1,g3 -> k-hi chunk

    uint32_t a_addr[4], b_base[2];
    #pragma unroll
    for (int mi = 0; mi < 4; mi++)
        a_addr[mi] = sb + OFF_A + (mrow + mi * 16 + ro_a) * 256;
    #pragma unroll
    for (int p = 0; p < 2; p++)
        b_base[p] = (jw + p * 16 + ro_b) * 256;

    float rowacc[8] = {0.f, 0.f, 0.f, 0.f, 0.f, 0.f, 0.f, 0.f};

    for (int t = 0; t < nt; t++) {
        if (t + 1 < nt) {
            copy_tile_async(sb + OFF_B + ((t + 1) & 1) * 32768, (jt0 + t + 1) * TN, tid);
            CP_COMMIT();
            CP_WAIT(1);                        // B(t) (and A) complete; B(t+1) in flight
        } else {
            CP_WAIT(0);
        }
        __syncthreads();

        const uint32_t bb = sb + OFF_B + (t & 1) * 32768;

        float c[4][4][4];
        #pragma unroll
        for (int mi = 0; mi < 4; mi++)
            #pragma unroll
            for (int ni = 0; ni < 4; ni++)
                #pragma unroll
                for (int q = 0; q < 4; q++) c[mi][ni][q] = 0.f;

        #pragma unroll
        for (int ks = 0; ks < 8; ks++) {
            const uint32_t chA = (uint32_t)(((ks * 2 + cg_a) ^ s7) << 4);
            const uint32_t chB = (uint32_t)(((ks * 2 + cg_b) ^ s7) << 4);
            uint32_t a[4][4], b[2][4];
            #pragma unroll
            for (int mi = 0; mi < 4; mi++) ldmatrix_x4(a[mi], a_addr[mi] + chA);
            #pragma unroll
            for (int p = 0; p < 2; p++)    ldmatrix_x4(b[p], bb + b_base[p] + chB);
            #pragma unroll
            for (int mi = 0; mi < 4; mi++)
                #pragma unroll
                for (int ni = 0; ni < 4; ni++)
                    mma_bf16(c[mi][ni], a[mi], &b[ni >> 1][(ni & 1) * 2]);
        }

        // epilogue: exp + row accumulate (padded cols give c==0 -> +1.0 each)
        #pragma unroll
        for (int mi = 0; mi < 4; mi++)
            #pragma unroll
            for (int ni = 0; ni < 4; ni++) {
                float2 e0 = up2(exp_pk(pk2(c[mi][ni][0], c[mi][ni][1])));
                float2 e1 = up2(exp_pk(pk2(c[mi][ni][2], c[mi][ni][3])));
                rowacc[mi * 2]     += e0.x + e0.y;
                rowacc[mi * 2 + 1] += e1.x + e1.y;
            }

        // correct for padded (j >= T) columns in the last j-tile
        const int j0 = (jt0 + t) * TN;
        if (j0 + TN > T) {
            int cnt = 0;
            #pragma unroll
            for (int ni = 0; ni < 4; ni++) {
                int col = j0 + jw + ni * 8 + 2 * (lane & 3);
                cnt += (col >= T) + (col + 1 >= T);
            }
            float fc = (float)cnt;
            #pragma unroll
            for (int q = 0; q < 8; q++) rowacc[q] -= fc;
        }
        __syncthreads();
    }

    // reduce over the 4 lanes sharing each row (lane&3)
    #pragma unroll
    for (int q = 0; q < 8; q++) {
        rowacc[q] += __shfl_xor_sync(0xffffffffu, rowacc[q], 1);
        rowacc[q] += __shfl_xor_sync(0xffffffffu, rowacc[q], 2);
    }
    float* red = (float*)smem;                 // reuse A region: red[4][128]
    if ((lane & 3) == 0) {
        int r = lane >> 2;
        #pragma unroll
        for (int mi = 0; mi < 4; mi++) {
            red[nq * 128 + mrow + mi * 16 + r]     = rowacc[mi * 2];
            red[nq * 128 + mrow + mi * 16 + r + 8] = rowacc[mi * 2 + 1];
        }
    }
    __syncthreads();
    if (tid < TM) {
        float s = red[tid] + red[128 + tid] + red[256 + tid] + red[384 + tid];
        g_part[blockIdx.y][i0 + tid] = s;
    }
}

// warp-per-block: exact fp32 in-block cosines + final log terms
__global__ __launch_bounds__(256) void pairs_kernel(float r, int T, int B) {
    const int lane = threadIdx.x & 31;
    const int wid  = threadIdx.x >> 5;
    const int b    = blockIdx.x * 8 + wid;
    float warp_term = 0.f;
    if (b < B) {
        float4 xr[BLK];
        #pragma unroll
        for (int m = 0; m < BLK; m++)
            xr[m] = *(const float4*)&g_xn[(b * BLK + m) * C_DIM + lane * 4];
        float cm[BLK][BLK];
        #pragma unroll
        for (int i = 0; i < BLK; i++)
            #pragma unroll
            for (int j = i; j < BLK; j++) {
                float s = xr[i].x * xr[j].x + xr[i].y * xr[j].y
                        + xr[i].z * xr[j].z + xr[i].w * xr[j].w;
                #pragma unroll
                for (int o = 16; o > 0; o >>= 1) s += __shfl_xor_sync(0xffffffffu, s, o);
                cm[i][j] = s; cm[j][i] = s;
            }
        float term = 0.f;
        #pragma unroll
        for (int i = 0; i < BLK; i++) {
            if (lane == i) {
                float es[BLK], bsum = 0.f;
                #pragma unroll
                for (int m = 0; m < BLK; m++) { es[m] = expf(cm[i][m]); bsum += es[m]; }
                float rs = 0.f;
                #pragma unroll
                for (int s = 0; s < NSPLIT; s++) rs += g_part[s][b * BLK + i];
                float negA = r * (rs - bsum);
                #pragma unroll
                for (int m = 0; m < BLK; m++)
                    if (m != i) term += logf(es[m] + negA) - cm[i][m];
            }
        }
        #pragma unroll
        for (int o = 16; o > 0; o >>= 1) term += __shfl_xor_sync(0xffffffffu, term, o);
        warp_term = term;
    }
    __shared__ float ws[8];
    if (lane == 0) ws[wid] = warp_term;
    __syncthreads();
    if (threadIdx.x == 0) {
        float s = 0.f;
        #pragma unroll
        for (int k = 0; k < 8; k++) s += ws[k];
        g_pairpart[blockIdx.x] = s;
    }
}

__global__ void finalize_kernel(const int* __restrict__ kuai2, int B, int ncta, float* out) {
    int lane = threadIdx.x;                    // 32
    double s = 0.0;
    for (int i = lane; i < ncta; i += 32) s += (double)g_pairpart[i];
    #pragma unroll
    for (int o = 16; o > 0; o >>= 1) s += __shfl_xor_sync(0xffffffffu, s, o);
    if (lane == 0) {
        int k2 = *kuai2;
        out[0] = (float)(s / ((double)B * (double)k2 * (double)(k2 - 1)));
    }
}

// ---------------- launch ----------------
extern "C" void kernel_launch(void* const* d_in, const int* in_sizes, int n_in,
                              void* d_out, int out_size) {
    const float* x     = (const float*)d_in[0];
    const int*   kuai2 = (const int*)d_in[1];

    int T = in_sizes[0] / C_DIM;
    int B = T / BLK;
    float r = (float)(2 * B - 2) / (float)(T - BLK);
    int ntM = (T + TM - 1) / TM;
    int ntN = (T + TN - 1) / TN;
    int ncta_pairs = (B + 7) / 8;

    cudaFuncSetAttribute(rowsum_mma, cudaFuncAttributeMaxDynamicSharedMemorySize, SMEM_DYN);

    normalize_kernel<<<T, C_DIM>>>(x, T);
    dim3 grid(ntM, NSPLIT);
    rowsum_mma<<<grid, 256, SMEM_DYN>>>(T, ntN);
    pairs_kernel<<<ncta_pairs, 256>>>(r, T, B);
    finalize_kernel<<<1, 32>>>(kuai2, B, ncta_pairs, (float*)d_out);
}